// round 2
// baseline (speedup 1.0000x reference)
#include <cuda_runtime.h>

// DTWLoss: B=64, T=1024, F=4 (only first 2 features used).
// Fused forward DP: propagate both the DTW cost C and the backtrace-path
// L1 loss L through the same anti-diagonal wavefront. L[T-1][T-1] is the
// per-batch loss; no explicit backtrace needed.

#define Tn 1024
#define Bn 64
#define Fdim 4
#define RPT 4                 // rows per thread
#define NTHREADS (Tn / RPT)   // 256
#define NWARPS (NTHREADS / 32)
#define INFV 1e30f

__device__ float g_losses[Bn];

__global__ void __launch_bounds__(NTHREADS, 1)
dtw_forward_kernel(const float* __restrict__ preds,
                   const float* __restrict__ targs,
                   const float* __restrict__ subcoef)
{
    __shared__ float sqx[Tn];
    __shared__ float sqy[Tn];
    __shared__ float bnd_c[2][NWARPS];
    __shared__ float bnd_L[2][NWARPS];

    const int b = blockIdx.x;
    const int t = threadIdx.x;
    const int lane = t & 31;
    const int warp = t >> 5;
    const int i0 = t * RPT;

    // stage q (targs) coords into smem
    const float* tb = targs + (size_t)b * Tn * Fdim;
    for (int j = t; j < Tn; j += NTHREADS) {
        float4 v = *(const float4*)(tb + j * Fdim);
        sqx[j] = v.x; sqy[j] = v.y;
    }
    // p (preds) rows owned by this thread -> registers
    const float* pb = preds + (size_t)b * Tn * Fdim;
    float px[RPT], py[RPT];
#pragma unroll
    for (int r = 0; r < RPT; r++) {
        float4 v = *(const float4*)(pb + (size_t)(i0 + r) * Fdim);
        px[r] = v.x; py[r] = v.y;
    }
    const float sc0 = subcoef[0];
    const float sc1 = subcoef[1];

    // DP state. c[r] = C(i0+r, j_r) after last processed diagonal;
    // cold[r] = one diagonal older (used as "diag" by row r+1).
    float c[RPT], L[RPT], cold[RPT], Lold[RPT];
    float qx[RPT], qy[RPT];
#pragma unroll
    for (int r = 0; r < RPT; r++) {
        c[r] = INFV; L[r] = 0.f; cold[r] = INFV; Lold[r] = 0.f;
        qx[r] = 0.f; qy[r] = 0.f;
    }
    if (t == 0) c[0] = 0.f;  // virtual C(0,-1)=0 so C(0,0)=D(0,0), L(0,0)=e(0,0)
    float diag0 = INFV, Ldiag0 = 0.f;

    // init boundary buffers (both parities) to "frozen INF" state
    if (t < 2 * NWARPS) {
        bnd_c[t / NWARPS][t % NWARPS] = INFV;
        bnd_L[t / NWARPS][t % NWARPS] = 0.f;
    }
    __syncthreads();

    for (int k = 0; k < 2 * Tn - 1; k++) {
        // neighbor-above boundary: its c[RPT-1], L[RPT-1] from iteration k-1
        float upc = __shfl_up_sync(0xffffffffu, c[RPT - 1], 1);
        float upL = __shfl_up_sync(0xffffffffu, L[RPT - 1], 1);
        if (lane == 0) {
            if (warp == 0) { upc = INFV; upL = 0.f; }
            else { upc = bnd_c[(k + 1) & 1][warp - 1]; upL = bnd_L[(k + 1) & 1][warp - 1]; }
        }

        const int j0 = k - i0;  // row 0's column this iteration
        if (j0 >= 0 && j0 - (RPT - 1) <= Tn - 1) {
            // shift q queue downward through the rows, load new head
#pragma unroll
            for (int r = RPT - 1; r >= 1; r--) { qx[r] = qx[r - 1]; qy[r] = qy[r - 1]; }
            if (j0 <= Tn - 1) { qx[0] = sqx[j0]; qy[0] = sqy[j0]; }

            // rows descending: reads of c[r-1]/cold[r-1] see pre-update values
#pragma unroll
            for (int r = RPT - 1; r >= 0; r--) {
                const int j = j0 - r;
                if (j >= 0 && j <= Tn - 1) {
                    const float cu = (r == 0) ? upc : c[r - 1];      // C(i-1, j)
                    const float cd = (r == 0) ? diag0 : cold[r - 1]; // C(i-1, j-1)
                    const float Lu = (r == 0) ? upL : L[r - 1];
                    const float Ld = (r == 0) ? Ldiag0 : Lold[r - 1];
                    const float cl = c[r];                           // C(i, j-1)
                    const float Ll = L[r];

                    const float dx = px[r] - qx[r];
                    const float dy = py[r] - qy[r];
                    const float dist = __fsqrt_rn(fmaf(dx, dx, dy * dy));

                    const float m = fminf(cd, fminf(cu, cl));
                    // argmin tie order: diag, up, left (matches jnp.argmin on [cd,cu,cl])
                    const bool pick_d = (cd <= cu) && (cd <= cl);
                    const bool pick_u = (cu <= cl);
                    const float Lp = pick_d ? Ld : (pick_u ? Lu : Ll);
                    const float e = fmaf(fabsf(dx), sc0, fabsf(dy) * sc1);

                    cold[r] = cl;   // becomes "diag" for row r+1 next iteration
                    Lold[r] = Ll;
                    c[r] = dist + m;
                    L[r] = e + Lp;
                }
            }
        }
        // track neighbor history for row 0's diag (safe unconditionally)
        diag0 = upc; Ldiag0 = upL;

        if (lane == 31) {
            bnd_c[k & 1][warp] = c[RPT - 1];
            bnd_L[k & 1][warp] = L[RPT - 1];
        }
        __syncthreads();
    }

    if (t == NTHREADS - 1) g_losses[b] = L[RPT - 1];
}

__global__ void reduce_kernel(float* __restrict__ out)
{
    const int t = threadIdx.x;  // 64 threads
    float v = g_losses[t];
#pragma unroll
    for (int o = 16; o > 0; o >>= 1) v += __shfl_down_sync(0xffffffffu, v, o);
    __shared__ float part[2];
    if ((t & 31) == 0) part[t >> 5] = v;
    __syncthreads();
    if (t == 0) out[0] = part[0] + part[1];
}

extern "C" void kernel_launch(void* const* d_in, const int* in_sizes, int n_in,
                              void* d_out, int out_size)
{
    const float* preds   = (const float*)d_in[0];
    const float* targs   = (const float*)d_in[1];
    const float* subcoef = (const float*)d_in[2];
    float* out = (float*)d_out;

    dtw_forward_kernel<<<Bn, NTHREADS>>>(preds, targs, subcoef);
    reduce_kernel<<<1, 64>>>(out);
}

// round 4
// speedup vs baseline: 1.3191x; 1.3191x over previous
#include <cuda_runtime.h>

// DTWLoss B=64, T=1024. Warp-pipelined column-sweep DP, fused path loss.
// Each batch split across 2 CTAs (rows 0-511 / 512-1023), pipelined via
// gmem chunks + release/acquire flags. Intra-CTA warps pipeline via named
// barriers every CW columns; intra-warp via shfl (1-column lane skew).

#define Tn 1024
#define Bn 64
#define CW 32                  // columns per sync chunk
#define NCHUNK (Tn / CW)       // 32
#define RPT 4                  // rows per lane
#define NWARP 4
#define NTH (NWARP * 32)       // 128 threads
#define HALF_ROWS 512
#define STEPS (Tn + 31)        // 1055
#define INFV 1e30f

__device__ float2   g_bnd[Bn][Tn];         // row-511 boundary (C, L)
__device__ unsigned g_flag[Bn][NCHUNK];    // per-chunk ready flags
__device__ float    g_losses[Bn];

__device__ __forceinline__ unsigned ld_acq(const unsigned* p) {
    unsigned v;
    asm volatile("ld.acquire.gpu.u32 %0, [%1];" : "=r"(v) : "l"(p) : "memory");
    return v;
}
__device__ __forceinline__ void st_rel(unsigned* p, unsigned v) {
    asm volatile("st.release.gpu.u32 [%0], %1;" :: "l"(p), "r"(v) : "memory");
}
#define BARSYNC(id) asm volatile("bar.sync %0, 64;" :: "r"(id) : "memory")

__global__ void init_kernel() {
    int i = blockIdx.x * blockDim.x + threadIdx.x;
    if (i < Bn * NCHUNK) ((unsigned*)g_flag)[i] = 0u;
}

__global__ void __launch_bounds__(NTH, 1)
dtw_kernel(const float* __restrict__ preds,
           const float* __restrict__ targs,
           const float* __restrict__ subcoef)
{
    __shared__ float2 sq[Tn];                    // target coords
    __shared__ float2 bnd[NWARP - 1][2][CW];     // intra-CTA warp boundaries
    __shared__ float2 hb[CW];                    // staged cross-CTA boundary chunk

    const int b    = blockIdx.x >> 1;
    const int hi   = blockIdx.x & 1;
    const int t    = threadIdx.x;
    const int lane = t & 31;
    const int warp = t >> 5;
    const int rowbase = hi * HALF_ROWS + warp * 128 + lane * RPT;

    const float* tb = targs + (size_t)b * Tn * 4;
    for (int j = t; j < Tn; j += NTH) {
        float4 v = *(const float4*)(tb + j * 4);
        sq[j] = make_float2(v.x, v.y);
    }
    const float* pb = preds + (size_t)b * Tn * 4;
    float px[RPT], py[RPT];
#pragma unroll
    for (int r = 0; r < RPT; r++) {
        float4 v = *(const float4*)(pb + (size_t)(rowbase + r) * 4);
        px[r] = v.x; py[r] = v.y;
    }
    const float sc0 = subcoef[0];
    const float sc1 = subcoef[1];

    float c[RPT], L[RPT];
#pragma unroll
    for (int r = 0; r < RPT; r++) { c[r] = INFV; L[r] = 0.f; }
    if (!hi && warp == 0 && lane == 0) c[0] = 0.f;  // virtual C(0,-1)=0
    float pupc = INFV, pupL = 0.f;                  // diag source for row 0

    __syncthreads();

    for (int s = 0; s < STEPS; ++s) {
        // boundary value from lane-1 (its row3 as of previous step = column j)
        float upc = __shfl_up_sync(0xffffffffu, c[RPT - 1], 1);
        float upL = __shfl_up_sync(0xffffffffu, L[RPT - 1], 1);

        // ---- consumer sync at chunk starts ----
        if (s < Tn && (s & (CW - 1)) == 0) {
            if (warp == 0) {
                if (hi) {
                    const unsigned* fp = &g_flag[b][s >> 5];
                    while (ld_acq(fp) == 0u) {}
                    hb[lane] = g_bnd[b][s + lane];   // stage chunk to smem
                    __syncwarp();
                }
            } else {
                BARSYNC(warp);   // wait on producer warp-1 (id = warp)
            }
        }

        if (lane == 0) {
            if (warp == 0) {
                if (hi) {
                    if (s < Tn) { float2 v = hb[s & (CW - 1)]; upc = v.x; upL = v.y; }
                } else { upc = INFV; upL = 0.f; }
            } else {
                if (s < Tn) {
                    float2 v = bnd[warp - 1][(s >> 5) & 1][s & (CW - 1)];
                    upc = v.x; upL = v.y;
                }
            }
        }

        const int j = s - lane;
        if (j >= 0 && j < Tn) {
            float2 q = sq[j];
            float dgc = pupc, dgL = pupL;   // C(base-1, j-1)
            float uc  = upc,  uL  = upL;    // C(base-1, j)
#pragma unroll
            for (int r = 0; r < RPT; ++r) {
                const float lc = c[r], lL = L[r];       // left = C(i, j-1)
                const float dx = px[r] - q.x;
                const float dy = py[r] - q.y;
                const float dist = __fsqrt_rn(fmaf(dx, dx, dy * dy));
                const float m = fminf(dgc, fminf(uc, lc));
                const bool pd = (dgc <= uc) && (dgc <= lc);
                const bool pu = (uc <= lc);
                const float Lp = pd ? dgL : (pu ? uL : lL);
                const float e  = fmaf(fabsf(dx), sc0, fabsf(dy) * sc1);
                c[r] = dist + m;
                L[r] = e + Lp;
                dgc = lc;   dgL = lL;       // old left becomes diag for next row
                uc  = c[r]; uL  = L[r];     // new value is up for next row
            }
            if (lane == 31) {
                if (warp < NWARP - 1)
                    bnd[warp][(j >> 5) & 1][j & (CW - 1)] = make_float2(c[RPT - 1], L[RPT - 1]);
                else if (!hi)
                    g_bnd[b][j] = make_float2(c[RPT - 1], L[RPT - 1]);
            }
        }
        pupc = upc; pupL = upL;

        // ---- producer sync after finishing a chunk (lane31 wrote col 32c+31) ----
        if (s >= CW + 30 && ((s - (CW + 30)) & (CW - 1)) == 0) {
            if (warp < NWARP - 1) {
                BARSYNC(warp + 1);  // release consumer warp+1 (id = warp+1)
            } else if (!hi) {
                if (lane == 31) {
                    __threadfence();
                    st_rel(&g_flag[b][(s - (CW + 30)) >> 5], 1u);
                }
            }
        }
    }

    if (hi && warp == NWARP - 1 && lane == 31)
        g_losses[b] = L[RPT - 1];
}

__global__ void reduce_kernel(float* __restrict__ out)
{
    const int t = threadIdx.x;  // 64 threads
    float v = g_losses[t];
#pragma unroll
    for (int o = 16; o > 0; o >>= 1) v += __shfl_down_sync(0xffffffffu, v, o);
    __shared__ float part[2];
    if ((t & 31) == 0) part[t >> 5] = v;
    __syncthreads();
    if (t == 0) out[0] = part[0] + part[1];
}

extern "C" void kernel_launch(void* const* d_in, const int* in_sizes, int n_in,
                              void* d_out, int out_size)
{
    const float* preds   = (const float*)d_in[0];
    const float* targs   = (const float*)d_in[1];
    const float* subcoef = (const float*)d_in[2];
    float* out = (float*)d_out;

    init_kernel<<<8, 256>>>();
    dtw_kernel<<<2 * Bn, NTH>>>(preds, targs, subcoef);
    reduce_kernel<<<1, 64>>>(out);
}

// round 5
// speedup vs baseline: 2.3833x; 1.8068x over previous
#include <cuda_runtime.h>

// DTWLoss B=64, T=1024. Warp-pipelined column-sweep DP with fused path loss.
// Branch-free 32-step inner loop (zero-padded inputs, INF-arithmetic fill),
// chunk-level sync only: named barriers between warps, release/acquire gmem
// flags between the two CTAs of each batch (rows 0-511 / 512-1023).

#define Tn 1024
#define Bn 64
#define CW 32
#define RPT 4
#define NWARP 4
#define NTH 128
#define NCH 33                // chunks 0..32; last has 31 steps (total 1055)
#define INFV 1e30f

__device__ float2   g_bnd[Bn][Tn + 64];   // +32 front pad (fill junk), +32 tail
__device__ unsigned g_flag[Bn][32];
__device__ float    g_losses[Bn];

__device__ __forceinline__ unsigned ld_acq(const unsigned* p) {
    unsigned v;
    asm volatile("ld.acquire.gpu.u32 %0, [%1];" : "=r"(v) : "l"(p) : "memory");
    return v;
}
__device__ __forceinline__ void st_rel(unsigned* p, unsigned v) {
    asm volatile("st.release.gpu.u32 [%0], %1;" :: "l"(p), "r"(v) : "memory");
}
#define BARSYNC(id) asm volatile("bar.sync %0, 64;" :: "r"(id) : "memory")

__global__ void init_kernel() {
    int i = blockIdx.x * blockDim.x + threadIdx.x;
    if (i < Bn * 32) ((unsigned*)g_flag)[i] = 0u;
}

__global__ void __launch_bounds__(NTH, 1)
dtw_kernel(const float* __restrict__ preds,
           const float* __restrict__ targs,
           const float* __restrict__ subcoef)
{
    __shared__ float2 sq_full[32 + Tn + 64];     // padded target coords
    __shared__ float2 bnd[NWARP - 1][128];       // 4-deep chunk ring per warp pair
    __shared__ float2 sHB[128];                  // staged cross-CTA chunks (hi warp0)
    __shared__ float2 sINF[128];                 // INF table (lo warp0) / hi-warp3 sink
    __shared__ float2 scratch[NTH];              // store sink for lanes != 31

    const int b    = blockIdx.x >> 1;
    const int hi   = blockIdx.x & 1;
    const int t    = threadIdx.x;
    const int lane = t & 31;
    const int warp = t >> 5;
    const int rowbase = hi * 512 + warp * 128 + lane * RPT;

    // ---- stage inputs ----
    const float* tb = targs + (size_t)b * Tn * 4;
    for (int j = t; j < Tn; j += NTH) {
        float4 v = *(const float4*)(tb + j * 4);
        sq_full[32 + j] = make_float2(v.x, v.y);
    }
    if (t < 32)  sq_full[t] = make_float2(0.f, 0.f);
    if (t < 64)  sq_full[32 + Tn + t] = make_float2(0.f, 0.f);
    if (t < 128) sINF[t] = make_float2(INFV, 0.f);

    const float* pb = preds + (size_t)b * Tn * 4;
    float px[RPT], py[RPT];
#pragma unroll
    for (int r = 0; r < RPT; r++) {
        float4 v = *(const float4*)(pb + (size_t)(rowbase + r) * 4);
        px[r] = v.x; py[r] = v.y;
    }
    const float sc0 = subcoef[0];
    const float sc1 = subcoef[1];

    float c[RPT], L[RPT];
#pragma unroll
    for (int r = 0; r < RPT; r++) { c[r] = INFV; L[r] = 0.f; }
    if (!hi && warp == 0 && lane == 0) c[0] = 0.f;   // virtual C(0,-1)=0

    float upc = INFV, upL = 0.f;     // pipelined shfl result for next step
    float p_uc = INFV, p_uL = 0.f;   // previous step's up (diag source, r=0)

    // boundary-read source for lane0
    const float2* bsrc = (warp == 0) ? (hi ? sHB : sINF) : bnd[warp - 1];
    // boundary-write target for lane31
    const bool smem_out = (warp < 3) || hi;
    float2* outp = (warp < 3) ? bnd[warp] : (hi ? sINF : (g_bnd[b] + 32));
    const int msk = smem_out ? 127 : -1;
    float2* myscratch = &scratch[t];
    const bool is_lane0  = (lane == 0);
    const bool is_lane31 = (lane == 31);

    __syncthreads();

    for (int cc = 0; cc < NCH; ++cc) {
        const int s0 = cc * CW;
        // ---- chunk prologue (consumer side) ----
        if (cc < 32) {
            if (warp == 0) {
                if (hi) {
                    const unsigned* fp = &g_flag[b][cc];
                    while (ld_acq(fp) == 0u) {}
                    sHB[((cc & 3) << 5) + lane] = g_bnd[b][32 + s0 + lane];
                    __syncwarp();
                }
            } else {
                BARSYNC(warp);
            }
        }
        const float2* bp = bsrc + ((cc & 3) << 5);
        const float2* qp = sq_full + 32 + s0 - lane;
        const int nsteps = (cc == NCH - 1) ? 31 : CW;

#pragma unroll 4
        for (int k = 0; k < nsteps; ++k) {
            float2 bv = bp[k];                       // uniform broadcast LDS
            const float uc = is_lane0 ? bv.x : upc;
            const float uL = is_lane0 ? bv.y : upL;
            float2 q = qp[k];

            float dgc = p_uc, dgL = p_uL;
            float ucr = uc,  uLr = uL;
#pragma unroll
            for (int r = 0; r < RPT; ++r) {
                const float lc = c[r], lL = L[r];
                const float dx = px[r] - q.x;
                const float dy = py[r] - q.y;
                const float dist = __fsqrt_rn(fmaf(dx, dx, dy * dy));
                const float m = fminf(dgc, fminf(ucr, lc));
                const bool pd = (dgc <= ucr) && (dgc <= lc);
                const bool pu = (ucr <= lc);
                const float Lp = pd ? dgL : (pu ? uLr : lL);
                const float e  = fmaf(fabsf(dx), sc0, fabsf(dy) * sc1);
                c[r] = dist + m;
                L[r] = e + Lp;
                dgc = lc;   dgL = lL;
                ucr = c[r]; uLr = L[r];
            }
            p_uc = uc; p_uL = uL;

            // branch-free boundary store: lane31 -> real target, others -> scratch
            const int j = s0 + k - 31;               // lane31's column
            float2* sta = is_lane31 ? (outp + (j & msk)) : myscratch;
            *sta = make_float2(c[RPT - 1], L[RPT - 1]);

            // pipelined shfl for next step
            upc = __shfl_up_sync(0xffffffffu, c[RPT - 1], 1);
            upL = __shfl_up_sync(0xffffffffu, L[RPT - 1], 1);
        }

        // ---- chunk epilogue (producer side): releases chunk cc-1 ----
        if (cc >= 1) {
            if (warp < NWARP - 1) {
                BARSYNC(warp + 1);
            } else if (!hi) {
                if (is_lane31) st_rel(&g_flag[b][cc - 1], 1u);
            }
        }
    }

    if (hi && warp == NWARP - 1 && is_lane31)
        g_losses[b] = L[RPT - 1];
}

__global__ void reduce_kernel(float* __restrict__ out)
{
    const int t = threadIdx.x;   // 64 threads
    float v = g_losses[t];
#pragma unroll
    for (int o = 16; o > 0; o >>= 1) v += __shfl_down_sync(0xffffffffu, v, o);
    __shared__ float part[2];
    if ((t & 31) == 0) part[t >> 5] = v;
    __syncthreads();
    if (t == 0) out[0] = part[0] + part[1];
}

extern "C" void kernel_launch(void* const* d_in, const int* in_sizes, int n_in,
                              void* d_out, int out_size)
{
    const float* preds   = (const float*)d_in[0];
    const float* targs   = (const float*)d_in[1];
    const float* subcoef = (const float*)d_in[2];
    float* out = (float*)d_out;

    init_kernel<<<8, 256>>>();
    dtw_kernel<<<2 * Bn, NTH>>>(preds, targs, subcoef);
    reduce_kernel<<<1, 64>>>(out);
}

// round 7
// speedup vs baseline: 2.3959x; 1.0053x over previous
#include <cuda_runtime.h>

// DTWLoss B=64, T=1024. Warp-pipelined column-sweep DP with fused path loss.
// One CTA per batch (8 warps x 32 lanes x 4 rows = 1024 rows). Warps form an
// 8-stage pipeline over 32-column chunks, synced with named barriers; lane
// boundary via shfl (1-column skew); warp boundary via smem rings (STS only).
// Steady state puts 2 active warps on each SMSP, hiding stall latency.
// Final reduction fused via atomic arrival counter (self-resetting).

#define Tn 1024
#define Bn 64
#define CW 32
#define RPT 4
#define NWARP 8
#define NTH 256
#define NCH 33                // chunks 0..32; last has 31 steps (total 1055)
#define INFV 1e30f

__device__ float    g_losses[Bn];
__device__ unsigned g_count;   // zero-initialized; last CTA resets it each launch

#define BARSYNC(id) asm volatile("bar.sync %0, 64;" :: "r"(id) : "memory")

__global__ void __launch_bounds__(NTH, 1)
dtw_kernel(const float* __restrict__ preds,
           const float* __restrict__ targs,
           const float* __restrict__ subcoef,
           float* __restrict__ out)
{
    __shared__ float2 sq_full[32 + Tn + 64];     // padded target coords
    __shared__ float2 bnd[NWARP - 1][128];       // 4-deep chunk ring per warp pair
    __shared__ float2 sINF[128];                 // INF boundary for warp 0
    __shared__ float2 scratch[NTH];              // store sink for lanes != 31 (+warp7)

    const int b    = blockIdx.x;
    const int t    = threadIdx.x;
    const int lane = t & 31;
    const int warp = t >> 5;
    const int rowbase = warp * 128 + lane * RPT;

    // ---- stage inputs ----
    const float* tb = targs + (size_t)b * Tn * 4;
    for (int j = t; j < Tn; j += NTH) {
        float4 v = *(const float4*)(tb + j * 4);
        sq_full[32 + j] = make_float2(v.x, v.y);
    }
    if (t < 32)  sq_full[t] = make_float2(0.f, 0.f);
    if (t < 64)  sq_full[32 + Tn + t] = make_float2(0.f, 0.f);
    if (t < 128) sINF[t] = make_float2(INFV, 0.f);

    const float* pb = preds + (size_t)b * Tn * 4;
    float px[RPT], py[RPT];
#pragma unroll
    for (int r = 0; r < RPT; r++) {
        float4 v = *(const float4*)(pb + (size_t)(rowbase + r) * 4);
        px[r] = v.x; py[r] = v.y;
    }
    const float sc0 = subcoef[0];
    const float sc1 = subcoef[1];

    float c[RPT], L[RPT];
#pragma unroll
    for (int r = 0; r < RPT; r++) { c[r] = INFV; L[r] = 0.f; }
    if (t == 0) c[0] = 0.f;          // virtual C(0,-1)=0 -> C(0,0)=D(0,0)

    float upc = INFV, upL = 0.f;     // pipelined shfl result for next step
    float p_uc = INFV, p_uL = 0.f;   // previous step's up (diag source, row 0)

    // boundary-read source for lane0 of this warp
    const float2* bsrc = (warp == 0) ? sINF : bnd[warp - 1];
    // boundary-write target for lane31 (all smem -> pure STS)
    float2* outp = (warp < NWARP - 1) ? bnd[warp] : &scratch[(NWARP - 1) * 32];
    const int msk = (warp < NWARP - 1) ? 127 : 31;
    float2* myscratch = &scratch[t];
    const bool is_lane0  = (lane == 0);
    const bool is_lane31 = (lane == 31);

    __syncthreads();

    for (int cc = 0; cc < NCH; ++cc) {
        const int s0 = cc * CW;
        // ---- chunk prologue: wait for producer warp (warp-1) ----
        if (warp > 0 && cc < 32) BARSYNC(warp);

        const float2* bp = bsrc + ((cc & 3) << 5);
        const float2* qp = sq_full + 32 + s0 - lane;
        const int nsteps = (cc == NCH - 1) ? 31 : CW;

#pragma unroll 4
        for (int k = 0; k < nsteps; ++k) {
            float2 bv = bp[k];                       // uniform broadcast LDS
            const float uc = is_lane0 ? bv.x : upc;
            const float uL = is_lane0 ? bv.y : upL;
            float2 q = qp[k];

            float dgc = p_uc, dgL = p_uL;
            float ucr = uc,  uLr = uL;
#pragma unroll
            for (int r = 0; r < RPT; ++r) {
                const float lc = c[r], lL = L[r];
                const float dx = px[r] - q.x;
                const float dy = py[r] - q.y;
                const float dist = __fsqrt_rn(fmaf(dx, dx, dy * dy));
                const float m = fminf(dgc, fminf(ucr, lc));
                const bool pd = (dgc <= ucr) && (dgc <= lc);
                const bool pu = (ucr <= lc);
                const float Lp = pd ? dgL : (pu ? uLr : lL);
                const float e  = fmaf(fabsf(dx), sc0, fabsf(dy) * sc1);
                c[r] = dist + m;
                L[r] = e + Lp;
                dgc = lc;   dgL = lL;
                ucr = c[r]; uLr = L[r];
            }
            p_uc = uc; p_uL = uL;

            // branch-free boundary store (both targets smem -> STS)
            const int j = s0 + k - 31;               // lane31's column
            float2* sta = is_lane31 ? (outp + (j & msk)) : myscratch;
            *sta = make_float2(c[RPT - 1], L[RPT - 1]);

            // pipelined shfl for next step
            upc = __shfl_up_sync(0xffffffffu, c[RPT - 1], 1);
            upL = __shfl_up_sync(0xffffffffu, L[RPT - 1], 1);
        }

        // ---- chunk epilogue: release consumer warp (warp+1), chunk cc-1 done ----
        if (warp < NWARP - 1 && cc >= 1) BARSYNC(warp + 1);
    }

    // ---- fused reduction: last-arriving CTA sums all batch losses ----
    if (t == NTH - 1) {
        g_losses[b] = L[RPT - 1];
        __threadfence();
        unsigned old = atomicAdd(&g_count, 1u);
        if (old == Bn - 1) {
            __threadfence();
            float s = 0.f;
            const volatile float* gl = g_losses;
#pragma unroll 8
            for (int i = 0; i < Bn; ++i) s += gl[i];
            out[0] = s;
            g_count = 0;     // reset for next graph replay (stream-ordered)
        }
    }
}

extern "C" void kernel_launch(void* const* d_in, const int* in_sizes, int n_in,
                              void* d_out, int out_size)
{
    const float* preds   = (const float*)d_in[0];
    const float* targs   = (const float*)d_in[1];
    const float* subcoef = (const float*)d_in[2];
    float* out = (float*)d_out;

    dtw_kernel<<<Bn, NTH>>>(preds, targs, subcoef, out);
}

// round 8
// speedup vs baseline: 3.7437x; 1.5625x over previous
#include <cuda_runtime.h>

// DTWLoss B=64, T=1024. Warp-pipelined column-sweep DP with fused path loss.
// 2 CTAs per batch (rows 0-511 / 512-1023), 8 warps x 32 lanes x 2 rows each.
// 16-stage pipeline: intra-CTA via smem rings + named barriers (2-chunk skew),
// cross-CTA via gmem boundary + self-resetting acquire/release flags.
// 2 warps per SMSP hide latency; 128 SMs active. sqrt.approx + chained-min
// cut the per-cell instruction count.

#define Tn 1024
#define Bn 64
#define CW 32
#define RPT 2
#define NWARP 8
#define NTH 256
#define INFV 1e30f

__device__ float2   g_bnd[Bn][Tn + 64];    // row-511 boundary; +32 front pad
__device__ unsigned g_flag[Bn][32];        // per-chunk ready flags (self-reset)
__device__ float2   g_dummy[2 * Bn][32];   // gmem store sink (lo warp7, lanes!=31)
__device__ float    g_losses[Bn];
__device__ unsigned g_count;               // zero-init; last CTA resets

__device__ __forceinline__ unsigned ld_acq(const unsigned* p) {
    unsigned v;
    asm volatile("ld.acquire.gpu.u32 %0, [%1];" : "=r"(v) : "l"(p) : "memory");
    return v;
}
__device__ __forceinline__ void st_rel(unsigned* p, unsigned v) {
    asm volatile("st.release.gpu.u32 [%0], %1;" :: "l"(p), "r"(v) : "memory");
}
__device__ __forceinline__ float fsqrt_ap(float x) {
    float r;
    asm("sqrt.approx.f32 %0, %1;" : "=f"(r) : "f"(x));
    return r;
}
#define BARSYNC(id) asm volatile("bar.sync %0, 64;" :: "r"(id) : "memory")

// One 32(or 31)-step chunk. GOUT: boundary store goes to gmem (lo warp7).
template<int NSTEPS, bool GOUT>
__device__ __forceinline__ void run_chunk(
    int s0, int lane, bool is_lane0, bool is_lane31,
    const float2* __restrict__ bp, const float2* __restrict__ qp,
    float2* outp, int msk, float2* sinkp,
    float px0, float py0, float px1, float py1, float sc0, float sc1,
    float& c0, float& c1, float& L0, float& L1,
    float& upc, float& upL, float& p_uc, float& p_uL)
{
#pragma unroll 4
    for (int k = 0; k < NSTEPS; ++k) {
        float2 bv = bp[k];                     // uniform broadcast LDS
        const float uc = is_lane0 ? bv.x : upc;
        const float uL = is_lane0 ? bv.y : upL;
        float2 q = qp[k];

        // distances + path-cost terms for both rows (independent, ILP)
        const float dx0 = px0 - q.x, dy0 = py0 - q.y;
        const float dx1 = px1 - q.x, dy1 = py1 - q.y;
        const float d0 = fsqrt_ap(fmaf(dx0, dx0, dy0 * dy0));
        const float d1 = fsqrt_ap(fmaf(dx1, dx1, dy1 * dy1));
        const float e0 = fmaf(fabsf(dx0), sc0, fabsf(dy0) * sc1);
        const float e1 = fmaf(fabsf(dx1), sc0, fabsf(dy1) * sc1);

        const float lc0 = c0, lL0 = L0, lc1 = c1, lL1 = L1;
        // row 0: diag=p_uc, up=uc, left=lc0. tie order: diag, up, left.
        const bool pu0 = (uc <= lc0);
        const float mv0 = pu0 ? uc : lc0;
        const float Lv0 = pu0 ? uL : lL0;
        const bool pd0 = (p_uc <= mv0);
        c0 = d0 + (pd0 ? p_uc : mv0);
        L0 = e0 + (pd0 ? p_uL : Lv0);
        // row 1: diag=lc0(old), up=c0(new), left=lc1
        const bool pu1 = (c0 <= lc1);
        const float mv1 = pu1 ? c0 : lc1;
        const float Lv1 = pu1 ? L0 : lL1;
        const bool pd1 = (lc0 <= mv1);
        c1 = d1 + (pd1 ? lc0 : mv1);
        L1 = e1 + (pd1 ? lL0 : Lv1);

        p_uc = uc; p_uL = uL;

        // branch-free boundary store (lane31 -> real target, others -> sink)
        const int j = s0 + k - 31;
        float2* sta;
        if (GOUT) sta = is_lane31 ? (outp + j) : sinkp;          // STG.64
        else      sta = is_lane31 ? (outp + (j & msk)) : sinkp;  // STS.64
        *sta = make_float2(c1, L1);

        // pipelined lane handoff for next step
        upc = __shfl_up_sync(0xffffffffu, c1, 1);
        upL = __shfl_up_sync(0xffffffffu, L1, 1);
    }
}

__global__ void __launch_bounds__(NTH, 1)
dtw_kernel(const float* __restrict__ preds,
           const float* __restrict__ targs,
           const float* __restrict__ subcoef,
           float* __restrict__ out)
{
    __shared__ float2 sq_full[32 + Tn + 64];   // padded target coords
    __shared__ float2 bnd[NWARP - 1][128];     // 4-deep chunk rings (warp w -> w+1)
    __shared__ float2 sHB[128];                // staged cross-CTA chunks (hi warp0)
    __shared__ float2 sINF[128];               // INF boundary (lo warp0)
    __shared__ float2 sink7[32];               // hi warp7 boundary dump ring
    __shared__ float2 scratch[NTH];            // smem store sink

    const int b    = blockIdx.x >> 1;
    const int hi   = blockIdx.x & 1;
    const int t    = threadIdx.x;
    const int lane = t & 31;
    const int warp = t >> 5;
    const int rowbase = hi * 512 + warp * 64 + lane * RPT;

    // ---- stage inputs ----
    const float* tb = targs + (size_t)b * Tn * 4;
    for (int j = t; j < Tn; j += NTH) {
        float4 v = *(const float4*)(tb + j * 4);
        sq_full[32 + j] = make_float2(v.x, v.y);
    }
    if (t < 32)  sq_full[t] = make_float2(0.f, 0.f);
    if (t < 64)  sq_full[32 + Tn + t] = make_float2(0.f, 0.f);
    if (t < 128) sINF[t] = make_float2(INFV, 0.f);

    const float* pb = preds + (size_t)b * Tn * 4;
    float4 p0 = *(const float4*)(pb + (size_t)rowbase * 4);
    float4 p1 = *(const float4*)(pb + (size_t)(rowbase + 1) * 4);
    const float px0 = p0.x, py0 = p0.y, px1 = p1.x, py1 = p1.y;
    const float sc0 = subcoef[0];
    const float sc1 = subcoef[1];

    float c0 = INFV, c1 = INFV, L0 = 0.f, L1 = 0.f;
    if (!hi && t == 0) c0 = 0.f;        // virtual C(0,-1)=0 -> C(0,0)=D(0,0)
    float upc = INFV, upL = 0.f;        // pipelined shfl result
    float p_uc = INFV, p_uL = 0.f;      // previous step's up = diag source

    const bool is_lane0  = (lane == 0);
    const bool is_lane31 = (lane == 31);
    const bool gout = (warp == NWARP - 1) && !hi;

    // lane0 boundary-read source
    const float2* bsrc = (warp == 0) ? (hi ? sHB : sINF) : bnd[warp - 1];
    // lane31 boundary-write target
    float2* outp;
    int msk;
    if (warp < NWARP - 1) { outp = bnd[warp]; msk = 127; }
    else if (hi)          { outp = sink7;     msk = 31; }
    else                  { outp = g_bnd[b] + 32; msk = -1; }
    float2* sinkp = gout ? &g_dummy[blockIdx.x][lane] : &scratch[t];

    __syncthreads();

    for (int cc = 0; cc <= 32; ++cc) {
        const int s0 = cc * CW;
        // ---- prologue: consumer waits for producer stage ----
        if (cc < 32) {
            if (warp == 0) {
                if (hi) {
                    unsigned* fp = &g_flag[b][cc];
                    if (is_lane0) { while (ld_acq(fp) == 0u) {} }
                    __syncwarp();
                    float2 v = __ldcg(&g_bnd[b][32 + s0 + lane]);
                    sHB[((cc & 3) << 5) + lane] = v;
                    if (is_lane0) *(volatile unsigned*)fp = 0u;   // self-reset
                    __syncwarp();
                }
            } else {
                BARSYNC(warp);
            }
        }

        const float2* bp = bsrc + ((cc & 3) << 5);
        const float2* qp = sq_full + 32 + s0 - lane;

        if (gout) {
            if (cc < 32) run_chunk<32, true >(s0, lane, is_lane0, is_lane31, bp, qp, outp, msk, sinkp,
                                              px0, py0, px1, py1, sc0, sc1, c0, c1, L0, L1, upc, upL, p_uc, p_uL);
            else         run_chunk<31, true >(s0, lane, is_lane0, is_lane31, bp, qp, outp, msk, sinkp,
                                              px0, py0, px1, py1, sc0, sc1, c0, c1, L0, L1, upc, upL, p_uc, p_uL);
        } else {
            if (cc < 32) run_chunk<32, false>(s0, lane, is_lane0, is_lane31, bp, qp, outp, msk, sinkp,
                                              px0, py0, px1, py1, sc0, sc1, c0, c1, L0, L1, upc, upL, p_uc, p_uL);
            else         run_chunk<31, false>(s0, lane, is_lane0, is_lane31, bp, qp, outp, msk, sinkp,
                                              px0, py0, px1, py1, sc0, sc1, c0, c1, L0, L1, upc, upL, p_uc, p_uL);
        }

        // ---- epilogue: producer release (chunk cc done -> consumer may run cc-1) ----
        if (cc >= 1) {
            if (warp < NWARP - 1) {
                BARSYNC(warp + 1);
            } else if (!hi) {
                if (is_lane31) st_rel(&g_flag[b][cc - 1], 1u);
            }
        }
    }

    // ---- fused reduction: hi CTAs only ----
    if (hi && t == NTH - 1) {
        g_losses[b] = L1;                 // row 1023, col 1023 (last real step)
        __threadfence();
        unsigned old = atomicAdd(&g_count, 1u);
        if (old == Bn - 1) {
            __threadfence();
            float s = 0.f;
            const volatile float* gl = g_losses;
#pragma unroll 8
            for (int i = 0; i < Bn; ++i) s += gl[i];
            out[0] = s;
            g_count = 0;                  // reset for next graph replay
        }
    }
}

extern "C" void kernel_launch(void* const* d_in, const int* in_sizes, int n_in,
                              void* d_out, int out_size)
{
    const float* preds   = (const float*)d_in[0];
    const float* targs   = (const float*)d_in[1];
    const float* subcoef = (const float*)d_in[2];
    float* out = (float*)d_out;

    dtw_kernel<<<2 * Bn, NTH>>>(preds, targs, subcoef, out);
}